// round 1
// baseline (speedup 1.0000x reference)
#include <cuda_runtime.h>
#include <math.h>

#define B_  4
#define S_  2048
#define H_  16
#define DK_ 64
#define D_  1024

// Scratch (device globals — allocation-free rule)
__device__ float g_q [B_*H_*S_*DK_];
__device__ float g_k [B_*H_*S_*DK_];
__device__ float g_v [B_*H_*S_*DK_];
__device__ float g_ao[B_*S_*D_];

// ---------------------------------------------------------------------------
// NT SGEMM: C[M,N] = A[M,K] * W[N,K]^T.  128x128 tile, BK=8, 256 thr, 8x8 micro.
// MODE 0: A = x, epilogue scatters into g_q/g_k/g_v ([b,h,s,dk] layout)
// MODE 1: A = g_ao, epilogue stores plain C (row stride D_)
// ---------------------------------------------------------------------------
template<int MODE>
__global__ void __launch_bounds__(256) sgemm_nt(const float* __restrict__ A,
                                                const float* __restrict__ W,
                                                float* __restrict__ C,
                                                int K) {
    __shared__ float As[8][132];
    __shared__ float Ws[8][132];
    const int tid = threadIdx.x;
    const int tx = tid & 15, ty = tid >> 4;
    const int bm = blockIdx.y, bn = blockIdx.x;
    if (MODE == 1) A = g_ao;
    const float* Ag = A + (size_t)bm * 128 * K;
    const float* Wg = W + (size_t)bn * 128 * K;
    const int lr = tid >> 1;
    const int lc = (tid & 1) * 4;

    float acc[8][8];
#pragma unroll
    for (int i = 0; i < 8; i++)
#pragma unroll
        for (int j = 0; j < 8; j++) acc[i][j] = 0.f;

    for (int kt = 0; kt < K; kt += 8) {
        float4 av = *(const float4*)(Ag + lr * K + kt + lc);
        float4 wv = *(const float4*)(Wg + lr * K + kt + lc);
        __syncthreads();
        As[lc+0][lr]=av.x; As[lc+1][lr]=av.y; As[lc+2][lr]=av.z; As[lc+3][lr]=av.w;
        Ws[lc+0][lr]=wv.x; Ws[lc+1][lr]=wv.y; Ws[lc+2][lr]=wv.z; Ws[lc+3][lr]=wv.w;
        __syncthreads();
#pragma unroll
        for (int k = 0; k < 8; k++) {
            float4 a0 = *(const float4*)&As[k][ty*4];
            float4 a1 = *(const float4*)&As[k][64 + ty*4];
            float4 b0 = *(const float4*)&Ws[k][tx*4];
            float4 b1 = *(const float4*)&Ws[k][64 + tx*4];
            float ar[8] = {a0.x,a0.y,a0.z,a0.w,a1.x,a1.y,a1.z,a1.w};
            float br[8] = {b0.x,b0.y,b0.z,b0.w,b1.x,b1.y,b1.z,b1.w};
#pragma unroll
            for (int i = 0; i < 8; i++)
#pragma unroll
                for (int j = 0; j < 8; j++)
                    acc[i][j] += ar[i] * br[j];
        }
    }

#pragma unroll
    for (int i = 0; i < 8; i++) {
        int r = bm*128 + ((i < 4) ? (ty*4 + i) : (64 + ty*4 + (i-4)));
#pragma unroll
        for (int jq = 0; jq < 2; jq++) {
            int cb = bn*128 + jq*64 + tx*4;
            float4 val = make_float4(acc[i][jq*4+0], acc[i][jq*4+1],
                                     acc[i][jq*4+2], acc[i][jq*4+3]);
            if (MODE == 0) {
                int which = cb >> 10;            // 0:q 1:k 2:v
                int h  = (cb >> 6) & 15;
                int d0 = cb & 63;
                int b  = r >> 11;
                int s  = r & 2047;
                float* dst = (which == 0) ? g_q : (which == 1) ? g_k : g_v;
                *(float4*)(dst + (((size_t)(b*H_ + h) * S_ + s) * DK_ + d0)) = val;
            } else {
                *(float4*)(C + (size_t)r * D_ + cb) = val;
            }
        }
    }
}

// ---------------------------------------------------------------------------
// RoPE in-place on g_q and g_k. One thread per (row, pair).
// ---------------------------------------------------------------------------
__global__ void rope_kernel() {
    const int NP = B_*H_*S_*32;           // pairs per tensor
    int idx = blockIdx.x * blockDim.x + threadIdx.x;
    if (idx >= 2 * NP) return;
    int t   = (idx >= NP) ? 1 : 0;
    int i   = idx - t * NP;
    int pr  = i & 31;
    int row = i >> 5;
    int s   = row & (S_ - 1);
    // inv_freq = 10000^(-(2*pr)/64) = 2^(-(pr/32)*log2(1e4))
    float invf = exp2f(-(float)pr * (13.28771237954945f / 32.0f));
    float ang = (float)s * invf;
    float sn, cs;
    sincosf(ang, &sn, &cs);
    float* base = (t ? g_k : g_q) + (size_t)row * DK_ + pr * 2;
    float x1 = base[0], x2 = base[1];
    base[0] = x1 * cs - x2 * sn;
    base[1] = x1 * sn + x2 * cs;
}

// ---------------------------------------------------------------------------
// Flash attention: BQ=BK=64, dk=64, 128 threads (8x16), causal + softcap.
// Online softmax, fp32. Output to g_ao in [b,s,h,dk] layout.
// ---------------------------------------------------------------------------
__global__ void __launch_bounds__(128) flash_kernel() {
    extern __shared__ float sm[];
    float* Qs = sm;                    // [64][68] transposed (k-major)
    float* Ks = sm + 64*68;            // [64][68] transposed (k-major)
    float* Vs = sm + 2*64*68;          // [64][64] natural
    float* Ps = sm + 2*64*68 + 64*64;  // [64][68] transposed (kv-major)

    const int tid = threadIdx.x;
    const int tx = tid & 7, ty = tid >> 3;
    const int q0 = blockIdx.x * 64;
    const int h = blockIdx.y, b = blockIdx.z;
    const size_t bh = (size_t)(b*H_ + h) * S_ * DK_;
    const float* Qg = g_q + bh + (size_t)q0 * DK_;
    const float* Kg = g_k + bh;
    const float* Vg = g_v + bh;

    // load Q tile transposed: Qs[k][i]
#pragma unroll
    for (int f = tid; f < 1024; f += 128) {
        int r = f >> 4, c4 = (f & 15) * 4;
        float4 v = *(const float4*)(Qg + r*64 + c4);
        Qs[(c4+0)*68 + r] = v.x;
        Qs[(c4+1)*68 + r] = v.y;
        Qs[(c4+2)*68 + r] = v.z;
        Qs[(c4+3)*68 + r] = v.w;
    }

    float m_i[4], l_i[4], o[4][8];
#pragma unroll
    for (int i = 0; i < 4; i++) {
        m_i[i] = -INFINITY; l_i[i] = 0.f;
#pragma unroll
        for (int j = 0; j < 8; j++) o[i][j] = 0.f;
    }

    const int nkt = q0 >> 6;
    for (int kt = 0; kt <= nkt; kt++) {
        __syncthreads();   // protect Ks/Vs from previous-iter readers
        const float* Kt = Kg + (size_t)kt * 64 * DK_;
        const float* Vt = Vg + (size_t)kt * 64 * DK_;
#pragma unroll
        for (int f = tid; f < 1024; f += 128) {
            int r = f >> 4, c4 = (f & 15) * 4;
            float4 kv = *(const float4*)(Kt + r*64 + c4);
            Ks[(c4+0)*68 + r] = kv.x;
            Ks[(c4+1)*68 + r] = kv.y;
            Ks[(c4+2)*68 + r] = kv.z;
            Ks[(c4+3)*68 + r] = kv.w;
            *(float4*)(Vs + r*64 + c4) = *(const float4*)(Vt + r*64 + c4);
        }
        __syncthreads();

        // S = Q K^T
        float sc[4][8];
#pragma unroll
        for (int i = 0; i < 4; i++)
#pragma unroll
            for (int j = 0; j < 8; j++) sc[i][j] = 0.f;
#pragma unroll 8
        for (int k = 0; k < 64; k++) {
            float4 a  = *(const float4*)&Qs[k*68 + ty*4];
            float4 b0 = *(const float4*)&Ks[k*68 + tx*4];
            float4 b1 = *(const float4*)&Ks[k*68 + 32 + tx*4];
            float ar[4] = {a.x, a.y, a.z, a.w};
            float br[8] = {b0.x,b0.y,b0.z,b0.w,b1.x,b1.y,b1.z,b1.w};
#pragma unroll
            for (int i = 0; i < 4; i++)
#pragma unroll
                for (int j = 0; j < 8; j++)
                    sc[i][j] += ar[i] * br[j];
        }

        // scale, soft-cap, causal mask
        const bool diag = (kt == nkt);
#pragma unroll
        for (int i = 0; i < 4; i++) {
            int ig = q0 + ty*4 + i;
#pragma unroll
            for (int j = 0; j < 8; j++) {
                int jg = kt*64 + ((j < 4) ? (tx*4 + j) : (32 + tx*4 + (j-4)));
                float v = sc[i][j] * 0.125f;       // 1/sqrt(64)
                v = 50.0f * tanhf(v * 0.02f);      // soft cap
                if (diag && jg > ig) v = -1e30f;
                sc[i][j] = v;
            }
        }

        // online softmax + P staging
#pragma unroll
        for (int i = 0; i < 4; i++) {
            float rmax = sc[i][0];
#pragma unroll
            for (int j = 1; j < 8; j++) rmax = fmaxf(rmax, sc[i][j]);
            rmax = fmaxf(rmax, __shfl_xor_sync(0xffffffffu, rmax, 1));
            rmax = fmaxf(rmax, __shfl_xor_sync(0xffffffffu, rmax, 2));
            rmax = fmaxf(rmax, __shfl_xor_sync(0xffffffffu, rmax, 4));
            float mn = fmaxf(m_i[i], rmax);
            float rs = 0.f;
#pragma unroll
            for (int j = 0; j < 8; j++) {
                sc[i][j] = __expf(sc[i][j] - mn);
                rs += sc[i][j];
            }
            rs += __shfl_xor_sync(0xffffffffu, rs, 1);
            rs += __shfl_xor_sync(0xffffffffu, rs, 2);
            rs += __shfl_xor_sync(0xffffffffu, rs, 4);
            float corr = __expf(m_i[i] - mn);
            l_i[i] = l_i[i] * corr + rs;
            m_i[i] = mn;
#pragma unroll
            for (int j = 0; j < 8; j++) o[i][j] *= corr;
#pragma unroll
            for (int j = 0; j < 8; j++) {
                int col = (j < 4) ? (tx*4 + j) : (32 + tx*4 + (j-4));
                Ps[col*68 + ty*4 + i] = sc[i][j];
            }
        }
        __syncthreads();

        // O += P V
#pragma unroll 8
        for (int j = 0; j < 64; j++) {
            float4 a  = *(const float4*)&Ps[j*68 + ty*4];
            float4 v0 = *(const float4*)&Vs[j*64 + tx*4];
            float4 v1 = *(const float4*)&Vs[j*64 + 32 + tx*4];
            float pr[4] = {a.x, a.y, a.z, a.w};
            float vr[8] = {v0.x,v0.y,v0.z,v0.w,v1.x,v1.y,v1.z,v1.w};
#pragma unroll
            for (int i = 0; i < 4; i++)
#pragma unroll
                for (int jj = 0; jj < 8; jj++)
                    o[i][jj] += pr[i] * vr[jj];
        }
    }

    // epilogue: normalize, write [b,s,h,dk]
#pragma unroll
    for (int i = 0; i < 4; i++) {
        float inv = 1.0f / l_i[i];
        int qi = q0 + ty*4 + i;
        float* dst = g_ao + ((size_t)(b*S_ + qi) * H_ + h) * DK_;
        float4 v0 = make_float4(o[i][0]*inv, o[i][1]*inv, o[i][2]*inv, o[i][3]*inv);
        float4 v1 = make_float4(o[i][4]*inv, o[i][5]*inv, o[i][6]*inv, o[i][7]*inv);
        *(float4*)(dst + tx*4)      = v0;
        *(float4*)(dst + 32 + tx*4) = v1;
    }
}

// ---------------------------------------------------------------------------
extern "C" void kernel_launch(void* const* d_in, const int* in_sizes, int n_in,
                              void* d_out, int out_size) {
    const float* x     = (const float*)d_in[0];   // [4,2048,1024]
    const float* w_qkv = (const float*)d_in[1];   // [3072,1024]
    const float* w_out = (const float*)d_in[2];   // [1024,1024]
    float* out = (float*)d_out;                   // [4,2048,1024]

    // 1) QKV projection with scatter into per-head layout
    sgemm_nt<0><<<dim3(24, 64), 256>>>(x, w_qkv, nullptr, 1024);

    // 2) RoPE on q, k
    rope_kernel<<<32768, 256>>>();

    // 3) Flash attention (68.6 KB dynamic smem)
    const int FLASH_SMEM = (2*64*68 + 64*64 + 64*68) * 4;
    cudaFuncSetAttribute(flash_kernel,
                         cudaFuncAttributeMaxDynamicSharedMemorySize, FLASH_SMEM);
    flash_kernel<<<dim3(S_/64, H_, B_), 128, FLASH_SMEM>>>();

    // 4) Output projection
    sgemm_nt<1><<<dim3(8, 64), 256>>>(nullptr, w_out, out, 1024);
}

// round 4
// speedup vs baseline: 1.3849x; 1.3849x over previous
#include <cuda_runtime.h>
#include <cuda_bf16.h>
#include <cstdint>
#include <math.h>

#define B_  4
#define S_  2048
#define H_  16
#define DK_ 64
#define D_  1024

// Scratch (device globals — allocation-free rule)
__device__ float g_q [B_*H_*S_*DK_];
__device__ float g_k [B_*H_*S_*DK_];
__device__ float g_v [B_*H_*S_*DK_];
__device__ float g_ao[B_*S_*D_];

// ======================= helpers ===========================================
__device__ __forceinline__ void mma_bf16(float* c,
                                         uint32_t a0, uint32_t a1, uint32_t a2, uint32_t a3,
                                         uint32_t b0, uint32_t b1) {
    asm volatile(
        "mma.sync.aligned.m16n8k16.row.col.f32.bf16.bf16.f32 "
        "{%0,%1,%2,%3}, {%4,%5,%6,%7}, {%8,%9}, {%0,%1,%2,%3};"
        : "+f"(c[0]), "+f"(c[1]), "+f"(c[2]), "+f"(c[3])
        : "r"(a0), "r"(a1), "r"(a2), "r"(a3), "r"(b0), "r"(b1));
}

// split a float pair into packed bf16x2 hi and lo (lo = x - hi, rounded)
__device__ __forceinline__ void cvt_hilo(float x, float y, uint32_t& hi, uint32_t& lo) {
    __nv_bfloat162 h = __floats2bfloat162_rn(x, y);
    float hx = __bfloat162float(h.x);
    float hy = __bfloat162float(h.y);
    __nv_bfloat162 l = __floats2bfloat162_rn(x - hx, y - hy);
    hi = *(uint32_t*)&h;
    lo = *(uint32_t*)&l;
}

// ---------------------------------------------------------------------------
// bf16x3 NT GEMM: C[M,N] = A[M,1024] * W[N,1024]^T, CTA 128x128, BK=32 fp32,
// 256 thr (8 warps 4Mx2N), warp tile 32x64. Error-compensated:
//   acc += Ahi*Whi + Ahi*Wlo + Alo*Whi   (bf16 m16n8k16, fp32 accum)
// smem: packed bf16x2 tiles [128][20] b32 for Ahi, Alo, Whi, Wlo (40KB).
// MODE 0: A = x, epilogue scatters into g_q/g_k/g_v; MODE 1: A = g_ao.
// ---------------------------------------------------------------------------
#define PST 20   // pairs per smem row (16 data + 4 pad) => conflict-free frags
#define MM_SMEM_BYTES (4 * 128 * PST * 4)   // 40960

template<int MODE>
__global__ void __launch_bounds__(256) mm_bf16x3(const float* __restrict__ A,
                                                 const float* __restrict__ W,
                                                 float* __restrict__ C) {
    extern __shared__ uint32_t smu[];
    uint32_t* Ahs = smu;
    uint32_t* Als = smu + 128*PST;
    uint32_t* Whs = smu + 2*128*PST;
    uint32_t* Wls = smu + 3*128*PST;

    const int tid = threadIdx.x;
    const int w   = tid >> 5;
    const int l   = tid & 31;
    const int wm  = w & 3;           // 0..3  (M)
    const int wn  = w >> 2;          // 0..1  (N)
    const int g   = l >> 2;          // 0..7
    const int tq  = l & 3;           // 0..3
    const int bm = blockIdx.y, bn = blockIdx.x;
    if (MODE == 1) A = g_ao;

    const float* Ag = A + (size_t)bm * 128 * 1024;
    const float* Wg = W + (size_t)bn * 128 * 1024;

    // load mapping: row = tid/2, quads gq..gq+3 (16 floats per matrix per thread)
    const int grow = tid >> 1;
    const int gq   = (tid & 1) * 4;

    float4 sa[4], sw[4];
    auto ldg_chunk = [&](int c) {
#pragma unroll
        for (int q = 0; q < 4; q++) {
            sa[q] = *(const float4*)(Ag + (size_t)grow * 1024 + c * 32 + (gq + q) * 4);
            sw[q] = *(const float4*)(Wg + (size_t)grow * 1024 + c * 32 + (gq + q) * 4);
        }
    };
    auto sts_chunk = [&]() {
#pragma unroll
        for (int q = 0; q < 4; q++) {
            int pb = grow * PST + 2 * (gq + q);
            uint32_t h0, l0, h1, l1;
            cvt_hilo(sa[q].x, sa[q].y, h0, l0);
            cvt_hilo(sa[q].z, sa[q].w, h1, l1);
            Ahs[pb] = h0; Ahs[pb + 1] = h1;
            Als[pb] = l0; Als[pb + 1] = l1;
            cvt_hilo(sw[q].x, sw[q].y, h0, l0);
            cvt_hilo(sw[q].z, sw[q].w, h1, l1);
            Whs[pb] = h0; Whs[pb + 1] = h1;
            Wls[pb] = l0; Wls[pb + 1] = l1;
        }
    };

    float acc[2][8][4];
#pragma unroll
    for (int mi = 0; mi < 2; mi++)
#pragma unroll
        for (int ni = 0; ni < 8; ni++)
#pragma unroll
            for (int r = 0; r < 4; r++) acc[mi][ni][r] = 0.f;

    const int row0 = wm * 32;
    const int col0 = wn * 64;

    ldg_chunk(0);
    sts_chunk();
    __syncthreads();

    for (int c = 0; c < 32; c++) {
        if (c + 1 < 32) ldg_chunk(c + 1);   // overlap with compute below

#pragma unroll
        for (int ks = 0; ks < 2; ks++) {
            const int kc = ks * 8;          // pair offset within row
            uint32_t ah[2][4], al[2][4];
#pragma unroll
            for (int mi = 0; mi < 2; mi++) {
                int ra = (row0 + mi * 16 + g) * PST + kc + tq;
                int rb = ra + 8 * PST;
                ah[mi][0] = Ahs[ra];     ah[mi][1] = Ahs[rb];
                ah[mi][2] = Ahs[ra + 4]; ah[mi][3] = Ahs[rb + 4];
                al[mi][0] = Als[ra];     al[mi][1] = Als[rb];
                al[mi][2] = Als[ra + 4]; al[mi][3] = Als[rb + 4];
            }
#pragma unroll
            for (int ni = 0; ni < 8; ni++) {
                int rn = (col0 + ni * 8 + g) * PST + kc + tq;
                uint32_t bh0 = Whs[rn], bh1 = Whs[rn + 4];
                uint32_t bl0 = Wls[rn], bl1 = Wls[rn + 4];
#pragma unroll
                for (int mi = 0; mi < 2; mi++) {
                    mma_bf16(acc[mi][ni], ah[mi][0], ah[mi][1], ah[mi][2], ah[mi][3], bh0, bh1);
                    mma_bf16(acc[mi][ni], ah[mi][0], ah[mi][1], ah[mi][2], ah[mi][3], bl0, bl1);
                    mma_bf16(acc[mi][ni], al[mi][0], al[mi][1], al[mi][2], al[mi][3], bh0, bh1);
                }
            }
        }
        __syncthreads();
        if (c + 1 < 32) {
            sts_chunk();
            __syncthreads();
        }
    }

    // Epilogue
#pragma unroll
    for (int mi = 0; mi < 2; mi++) {
#pragma unroll
        for (int half = 0; half < 2; half++) {
            int r = bm * 128 + row0 + mi * 16 + g + half * 8;
#pragma unroll
            for (int ni = 0; ni < 8; ni++) {
                int cb = bn * 128 + col0 + ni * 8 + 2 * tq;
                float2 val = make_float2(acc[mi][ni][half * 2 + 0],
                                         acc[mi][ni][half * 2 + 1]);
                if (MODE == 0) {
                    int which = cb >> 10;          // 0:q 1:k 2:v
                    int h  = (cb >> 6) & 15;
                    int d0 = cb & 63;
                    int b  = r >> 11;
                    int s  = r & 2047;
                    float* dst = (which == 0) ? g_q : (which == 1) ? g_k : g_v;
                    *(float2*)(dst + (((size_t)(b * H_ + h) * S_ + s) * DK_ + d0)) = val;
                } else {
                    *(float2*)(C + (size_t)r * D_ + cb) = val;
                }
            }
        }
    }
}

// ---------------------------------------------------------------------------
// RoPE in-place on g_q and g_k. One thread per (row, pair).
// ---------------------------------------------------------------------------
__global__ void rope_kernel() {
    const int NP = B_*H_*S_*32;           // pairs per tensor
    int idx = blockIdx.x * blockDim.x + threadIdx.x;
    if (idx >= 2 * NP) return;
    int t   = (idx >= NP) ? 1 : 0;
    int i   = idx - t * NP;
    int pr  = i & 31;
    int row = i >> 5;
    int s   = row & (S_ - 1);
    float invf = exp2f(-(float)pr * (13.28771237954945f / 32.0f));
    float ang = (float)s * invf;
    float sn, cs;
    sincosf(ang, &sn, &cs);
    float* base = (t ? g_k : g_q) + (size_t)row * DK_ + pr * 2;
    float x1 = base[0], x2 = base[1];
    base[0] = x1 * cs - x2 * sn;
    base[1] = x1 * sn + x2 * cs;
}

// ---------------------------------------------------------------------------
// Flash attention: BQ=BK=64, dk=64, 128 threads (8x16), causal + softcap.
// Online softmax, fp32. Output to g_ao in [b,s,h,dk] layout.
// ---------------------------------------------------------------------------
__global__ void __launch_bounds__(128) flash_kernel() {
    extern __shared__ float smf[];
    float* Qs = smf;                    // [64][68] transposed (k-major)
    float* Ks = smf + 64*68;            // [64][68] transposed (k-major)
    float* Vs = smf + 2*64*68;          // [64][64] natural
    float* Ps = smf + 2*64*68 + 64*64;  // [64][68] transposed (kv-major)

    const int tid = threadIdx.x;
    const int tx = tid & 7, ty = tid >> 3;
    const int q0 = blockIdx.x * 64;
    const int h = blockIdx.y, b = blockIdx.z;
    const size_t bh = (size_t)(b*H_ + h) * S_ * DK_;
    const float* Qg = g_q + bh + (size_t)q0 * DK_;
    const float* Kg = g_k + bh;
    const float* Vg = g_v + bh;

#pragma unroll
    for (int f = tid; f < 1024; f += 128) {
        int r = f >> 4, c4 = (f & 15) * 4;
        float4 v = *(const float4*)(Qg + r*64 + c4);
        Qs[(c4+0)*68 + r] = v.x;
        Qs[(c4+1)*68 + r] = v.y;
        Qs[(c4+2)*68 + r] = v.z;
        Qs[(c4+3)*68 + r] = v.w;
    }

    float m_i[4], l_i[4], o[4][8];
#pragma unroll
    for (int i = 0; i < 4; i++) {
        m_i[i] = -INFINITY; l_i[i] = 0.f;
#pragma unroll
        for (int j = 0; j < 8; j++) o[i][j] = 0.f;
    }

    const int nkt = q0 >> 6;
    for (int kt = 0; kt <= nkt; kt++) {
        __syncthreads();
        const float* Kt = Kg + (size_t)kt * 64 * DK_;
        const float* Vt = Vg + (size_t)kt * 64 * DK_;
#pragma unroll
        for (int f = tid; f < 1024; f += 128) {
            int r = f >> 4, c4 = (f & 15) * 4;
            float4 kv = *(const float4*)(Kt + r*64 + c4);
            Ks[(c4+0)*68 + r] = kv.x;
            Ks[(c4+1)*68 + r] = kv.y;
            Ks[(c4+2)*68 + r] = kv.z;
            Ks[(c4+3)*68 + r] = kv.w;
            *(float4*)(Vs + r*64 + c4) = *(const float4*)(Vt + r*64 + c4);
        }
        __syncthreads();

        float sc[4][8];
#pragma unroll
        for (int i = 0; i < 4; i++)
#pragma unroll
            for (int j = 0; j < 8; j++) sc[i][j] = 0.f;
#pragma unroll 8
        for (int k = 0; k < 64; k++) {
            float4 a  = *(const float4*)&Qs[k*68 + ty*4];
            float4 b0 = *(const float4*)&Ks[k*68 + tx*4];
            float4 b1 = *(const float4*)&Ks[k*68 + 32 + tx*4];
            float ar[4] = {a.x, a.y, a.z, a.w};
            float br[8] = {b0.x,b0.y,b0.z,b0.w,b1.x,b1.y,b1.z,b1.w};
#pragma unroll
            for (int i = 0; i < 4; i++)
#pragma unroll
                for (int j = 0; j < 8; j++)
                    sc[i][j] += ar[i] * br[j];
        }

        const bool diag = (kt == nkt);
#pragma unroll
        for (int i = 0; i < 4; i++) {
            int ig = q0 + ty*4 + i;
#pragma unroll
            for (int j = 0; j < 8; j++) {
                int jg = kt*64 + ((j < 4) ? (tx*4 + j) : (32 + tx*4 + (j-4)));
                float v = sc[i][j] * 0.125f;
                v = 50.0f * tanhf(v * 0.02f);
                if (diag && jg > ig) v = -1e30f;
                sc[i][j] = v;
            }
        }

#pragma unroll
        for (int i = 0; i < 4; i++) {
            float rmax = sc[i][0];
#pragma unroll
            for (int j = 1; j < 8; j++) rmax = fmaxf(rmax, sc[i][j]);
            rmax = fmaxf(rmax, __shfl_xor_sync(0xffffffffu, rmax, 1));
            rmax = fmaxf(rmax, __shfl_xor_sync(0xffffffffu, rmax, 2));
            rmax = fmaxf(rmax, __shfl_xor_sync(0xffffffffu, rmax, 4));
            float mn = fmaxf(m_i[i], rmax);
            float rs = 0.f;
#pragma unroll
            for (int j = 0; j < 8; j++) {
                sc[i][j] = __expf(sc[i][j] - mn);
                rs += sc[i][j];
            }
            rs += __shfl_xor_sync(0xffffffffu, rs, 1);
            rs += __shfl_xor_sync(0xffffffffu, rs, 2);
            rs += __shfl_xor_sync(0xffffffffu, rs, 4);
            float corr = __expf(m_i[i] - mn);
            l_i[i] = l_i[i] * corr + rs;
            m_i[i] = mn;
#pragma unroll
            for (int j = 0; j < 8; j++) o[i][j] *= corr;
#pragma unroll
            for (int j = 0; j < 8; j++) {
                int col = (j < 4) ? (tx*4 + j) : (32 + tx*4 + (j-4));
                Ps[col*68 + ty*4 + i] = sc[i][j];
            }
        }
        __syncthreads();

#pragma unroll 8
        for (int j = 0; j < 64; j++) {
            float4 a  = *(const float4*)&Ps[j*68 + ty*4];
            float4 v0 = *(const float4*)&Vs[j*64 + tx*4];
            float4 v1 = *(const float4*)&Vs[j*64 + 32 + tx*4];
            float pr[4] = {a.x, a.y, a.z, a.w};
            float vr[8] = {v0.x,v0.y,v0.z,v0.w,v1.x,v1.y,v1.z,v1.w};
#pragma unroll
            for (int i = 0; i < 4; i++)
#pragma unroll
                for (int jj = 0; jj < 8; jj++)
                    o[i][jj] += pr[i] * vr[jj];
        }
    }

#pragma unroll
    for (int i = 0; i < 4; i++) {
        float inv = 1.0f / l_i[i];
        int qi = q0 + ty*4 + i;
        float* dst = g_ao + ((size_t)(b*S_ + qi) * H_ + h) * DK_;
        float4 v0 = make_float4(o[i][0]*inv, o[i][1]*inv, o[i][2]*inv, o[i][3]*inv);
        float4 v1 = make_float4(o[i][4]*inv, o[i][5]*inv, o[i][6]*inv, o[i][7]*inv);
        *(float4*)(dst + tx*4)      = v0;
        *(float4*)(dst + 32 + tx*4) = v1;
    }
}

// ---------------------------------------------------------------------------
extern "C" void kernel_launch(void* const* d_in, const int* in_sizes, int n_in,
                              void* d_out, int out_size) {
    const float* x     = (const float*)d_in[0];   // [4,2048,1024]
    const float* w_qkv = (const float*)d_in[1];   // [3072,1024]
    const float* w_out = (const float*)d_in[2];   // [1024,1024]
    float* out = (float*)d_out;                   // [4,2048,1024]

    cudaFuncSetAttribute(mm_bf16x3<0>, cudaFuncAttributeMaxDynamicSharedMemorySize, MM_SMEM_BYTES);
    cudaFuncSetAttribute(mm_bf16x3<1>, cudaFuncAttributeMaxDynamicSharedMemorySize, MM_SMEM_BYTES);

    // 1) QKV projection (bf16x3 mma.sync) with scatter into per-head layout
    mm_bf16x3<0><<<dim3(24, 64), 256, MM_SMEM_BYTES>>>(x, w_qkv, nullptr);

    // 2) RoPE on q, k
    rope_kernel<<<32768, 256>>>();

    // 3) Flash attention (68.6 KB dynamic smem)
    const int FLASH_SMEM = (2*64*68 + 64*64 + 64*68) * 4;
    cudaFuncSetAttribute(flash_kernel,
                         cudaFuncAttributeMaxDynamicSharedMemorySize, FLASH_SMEM);
    flash_kernel<<<dim3(S_/64, H_, B_), 128, FLASH_SMEM>>>();

    // 4) Output projection (bf16x3 mma.sync)
    mm_bf16x3<1><<<dim3(8, 64), 256, MM_SMEM_BYTES>>>(nullptr, w_out, out);
}